// round 8
// baseline (speedup 1.0000x reference)
#include <cuda_runtime.h>
#include <cuda_fp16.h>
#include <stdint.h>

#define BATCH 100000
#define SEQ   28
#define IND   28
#define HID   64
#define OUTD  10
#define TPB   64
#define MTILE 64                            // 64 batch rows per CTA (32 per warp)
#define NGRID ((BATCH + MTILE - 1)/MTILE)   // 1563

// ---------------- shared memory ----------------
// B fragments as ldmatrix-ready 8x8 f16 matrices (layout identical to R5/R7).
struct SmemLayout {
    __half bxm[2 * 12 * 256];     // W_ih frags: 12288 B
    __half bhm[4 * 12 * 256];     // W_hh frags: 24576 B
    uint32_t bias_frag[32 * 4];   // f16x2 bias per (nt, q): cols (nt&7)*8+2q, +1
    float wout[OUTD][HID];
    float bout[OUTD];
};
#define OFF_BXM 0
#define OFF_BHM (2 * 12 * 512)
#define OFF_BF  (OFF_BHM + 4 * 12 * 512)

// ---------------- helpers ----------------
__device__ __forceinline__ uint32_t smem_u32(const void* p) {
    uint32_t a;
    asm("{ .reg .u64 t; cvta.to.shared.u64 t, %1; cvt.u32.u64 %0, t; }" : "=r"(a) : "l"(p));
    return a;
}
__device__ __forceinline__ uint32_t pack_f16(float e0, float e1) {
    uint32_t r;
    asm("cvt.rn.f16x2.f32 %0, %1, %2;" : "=r"(r) : "f"(e1), "f"(e0));
    return r;
}
__device__ __forceinline__ float2 unpack_f16(uint32_t p) {
    __half2 h = *reinterpret_cast<__half2*>(&p);
    return __half22float2(h);
}
__device__ __forceinline__ void ldsm_x4(uint32_t addr, uint32_t& r0, uint32_t& r1,
                                        uint32_t& r2, uint32_t& r3) {
    asm volatile("ldmatrix.sync.aligned.m8n8.x4.shared.b16 {%0,%1,%2,%3}, [%4];"
                 : "=r"(r0), "=r"(r1), "=r"(r2), "=r"(r3) : "r"(addr));
}
// f16-accumulator mma: C/D are 2x f16x2 regs
__device__ __forceinline__ void mma_h(uint32_t* c, const uint32_t* a, uint32_t b0, uint32_t b1) {
    asm volatile(
        "mma.sync.aligned.m16n8k16.row.col.f16.f16.f16.f16 "
        "{%0,%1}, {%2,%3,%4,%5}, {%6,%7}, {%0,%1};"
        : "+r"(c[0]), "+r"(c[1])
        : "r"(a[0]), "r"(a[1]), "r"(a[2]), "r"(a[3]), "r"(b0), "r"(b1));
}
__device__ __forceinline__ uint32_t tanh2u(uint32_t x) {
    uint32_t y;
    asm("tanh.approx.f16x2 %0, %1;" : "=r"(y) : "r"(x));
    return y;
}
__device__ __forceinline__ __half2 u2h(uint32_t u) { return *reinterpret_cast<__half2*>(&u); }
__device__ __forceinline__ uint32_t h2u(__half2 h) { return *reinterpret_cast<uint32_t*>(&h); }
__device__ __forceinline__ __half2 sig2(__half2 x) {
    const __half2 half_ = __float2half2_rn(0.5f);
    return __hfma2(half_, u2h(tanh2u(h2u(__hmul2(x, half_)))), half_);
}
// full GRU cell on a pair of hidden units (all f16x2, inputs are raw acc regs)
__device__ __forceinline__ uint32_t gru2(uint32_t rs, uint32_t zs, uint32_t is,
                                         uint32_t hs, uint32_t ho) {
    __half2 r = sig2(u2h(rs));
    __half2 z = sig2(u2h(zs));
    __half2 n = u2h(tanh2u(h2u(__hfma2(r, u2h(hs), u2h(is)))));
    return h2u(__hfma2(z, __hsub2(u2h(ho), n), n));   // (1-z)*n + z*h
}

__global__ void __launch_bounds__(TPB, 4)
gru_mma_kernel(const float* __restrict__ x,
               const float* __restrict__ Wih,
               const float* __restrict__ Whh,
               const float* __restrict__ bih,
               const float* __restrict__ bhh,
               const float* __restrict__ Wout,
               const float* __restrict__ bout,
               float* __restrict__ out)
{
    extern __shared__ char smraw[];
    SmemLayout* sm = (SmemLayout*)smraw;
    const int tid = threadIdx.x;

    // ---- stage W_ih fragments ----
    for (int s = tid; s < 2 * 12 * 256; s += TPB) {
        int kk = s & 7, g = (s >> 3) & 7, mat = (s >> 6) & 3;
        int blk = s >> 8;
        int pair = blk % 12, kt = blk / 12;
        int n = pair * 16 + (mat >> 1) * 8 + g;
        int k = kt * 16 + (mat & 1) * 8 + kk;
        float v = (k < IND) ? Wih[n * IND + k] : 0.0f;
        sm->bxm[s] = __float2half_rn(v);
    }
    // ---- stage W_hh fragments ----
    for (int s = tid; s < 4 * 12 * 256; s += TPB) {
        int kk = s & 7, g = (s >> 3) & 7, mat = (s >> 6) & 3;
        int blk = s >> 8;
        int pair = blk % 12, kt = blk / 12;
        int ntl = pair * 2 + (mat >> 1);
        int ngl = (ntl < 16 ? ntl : ntl + 8) * 8 + g;
        int row = (ngl < 128) ? ngl : ngl - 64;
        int k = kt * 16 + (mat & 1) * 8 + kk;
        sm->bhm[s] = __float2half_rn(Whh[row * HID + k]);
    }
    // ---- bias table (f16x2) in fragment order: nt 0-7 r, 8-15 z, 16-23 i_n, 24-31 h_n ----
    for (int s = tid; s < 32 * 4; s += TPB) {
        int nt = s >> 2, qq = s & 3;
        int j = (nt & 7) * 8 + 2 * qq;
        float b0, b1;
        if (nt < 8)       { b0 = bih[j] + bhh[j];         b1 = bih[j+1] + bhh[j+1]; }
        else if (nt < 16) { b0 = bih[64+j] + bhh[64+j];   b1 = bih[64+j+1] + bhh[64+j+1]; }
        else if (nt < 24) { b0 = bih[128+j];              b1 = bih[128+j+1]; }
        else              { b0 = bhh[128+j];              b1 = bhh[128+j+1]; }
        sm->bias_frag[s] = pack_f16(b0, b1);
    }
    for (int i = tid; i < OUTD * HID; i += TPB) ((float*)sm->wout)[i] = Wout[i];
    for (int i = tid; i < OUTD; i += TPB) sm->bout[i] = bout[i];
    __syncthreads();

    const int lane = tid & 31;
    const int wid = tid >> 5;
    const int q = lane & 3, g = lane >> 2;
    const int rowbase = blockIdx.x * MTILE + wid * 32;
    // warp-uniform validity: only CTA 1562 / warp 1 is fully out of range
    const bool wvalid = rowbase < BATCH;

    const uint32_t smb = smem_u32(smraw);
    const uint32_t bx_base = smb + OFF_BXM + (uint32_t)lane * 16u;
    const uint32_t bh_base = smb + OFF_BHM + (uint32_t)lane * 16u;
    const uint32_t bf_base = smb + OFF_BF + (uint32_t)q * 4u;

    // one base pointer; row offsets are compile-time constants
    const float* xg = x + (size_t)((wvalid ? rowbase : 0) + g) * (SEQ * IND);

    uint32_t acc[2][32][2];     // f16x2 accumulators (raw regs)
    uint32_t Ax[2][2][4], Ah[2][4][4];
#pragma unroll
    for (int m = 0; m < 2; m++)
#pragma unroll
        for (int kt = 0; kt < 4; kt++)
#pragma unroll
            for (int r = 0; r < 4; r++) Ah[m][kt][r] = 0u;

#pragma unroll 1
    for (int t = 0; t < SEQ; t++) {
        const float* xt = xg + t * IND;

        // ---- load x_t and convert immediately (no persistent f32 staging) ----
        // A frag reg ra: 0 = row g / k lo-half, 1 = row g+8 / k lo, 2 = row g / k hi, 3 = row g+8 / k hi
#pragma unroll
        for (int m = 0; m < 2; m++) {
            const float* xm = xt + m * 16 * (SEQ * IND);
#pragma unroll
            for (int kt = 0; kt < 2; kt++)
#pragma unroll
                for (int half = 0; half < 2; half++) {
                    const int kb = kt * 16 + 2 * q + half * 8;
                    float2 p0 = make_float2(0.0f, 0.0f), p1 = p0;
                    if (kb < IND) {
                        p0 = *(const float2*)(xm + kb);
                        p1 = *(const float2*)(xm + 8 * (SEQ * IND) + kb);
                    }
                    Ax[m][kt][half * 2 + 0] = pack_f16(p0.x, p0.y);
                    Ax[m][kt][half * 2 + 1] = pack_f16(p1.x, p1.y);
                }
        }

        // ---- init accumulators from f16x2 bias table ----
#pragma unroll
        for (int nt = 0; nt < 32; nt++) {
            uint32_t bf;
            asm volatile("ld.shared.b32 %0, [%1];" : "=r"(bf)
                         : "r"(bf_base + (uint32_t)nt * 16u));
            acc[0][nt][0] = bf; acc[0][nt][1] = bf;
            acc[1][nt][0] = bf; acc[1][nt][1] = bf;
        }

        // ---- h GEMM: D[:,{0:128,192:256}] += h @ W_hh^T ----
#pragma unroll
        for (int kt = 0; kt < 4; kt++) {
#pragma unroll
            for (int p = 0; p < 12; p++) {
                uint32_t b0, b1, b2, b3;
                ldsm_x4(bh_base + (uint32_t)(kt * 12 + p) * 512u, b0, b1, b2, b3);
                const int ntl_e = 2 * p, ntl_o = 2 * p + 1;
                const int nt_e = (ntl_e < 16) ? ntl_e : ntl_e + 8;
                const int nt_o = (ntl_o < 16) ? ntl_o : ntl_o + 8;
                mma_h(acc[0][nt_e], Ah[0][kt], b0, b1);
                mma_h(acc[1][nt_e], Ah[1][kt], b0, b1);
                mma_h(acc[0][nt_o], Ah[0][kt], b2, b3);
                mma_h(acc[1][nt_o], Ah[1][kt], b2, b3);
            }
        }

        // ---- x GEMM: D[:,0:192] += x @ W_ih^T ----
#pragma unroll
        for (int kt = 0; kt < 2; kt++) {
#pragma unroll
            for (int p = 0; p < 12; p++) {
                uint32_t b0, b1, b2, b3;
                ldsm_x4(bx_base + (uint32_t)(kt * 12 + p) * 512u, b0, b1, b2, b3);
                mma_h(acc[0][2 * p],     Ax[0][kt], b0, b1);
                mma_h(acc[1][2 * p],     Ax[1][kt], b0, b1);
                mma_h(acc[0][2 * p + 1], Ax[0][kt], b2, b3);
                mma_h(acc[1][2 * p + 1], Ax[1][kt], b2, b3);
            }
        }

        // ---- epilogue: all-f16x2 gates directly on acc regs; h_new -> Ah ----
#pragma unroll
        for (int m = 0; m < 2; m++) {
#pragma unroll
            for (int i = 0; i < 8; i++) {
                const int kt = i >> 1;
                const int ra = (i & 1) * 2;
                Ah[m][kt][ra]     = gru2(acc[m][i][0], acc[m][8 + i][0],
                                         acc[m][16 + i][0], acc[m][24 + i][0],
                                         Ah[m][kt][ra]);
                Ah[m][kt][ra + 1] = gru2(acc[m][i][1], acc[m][8 + i][1],
                                         acc[m][16 + i][1], acc[m][24 + i][1],
                                         Ah[m][kt][ra + 1]);
            }
        }
    }

    // ---- output projection: out = hT @ W_out^T + b_out ----
    if (wvalid) {
#pragma unroll
        for (int m = 0; m < 2; m++) {
            float hf[8][4];
#pragma unroll
            for (int i = 0; i < 8; i++) {
                const int kt = i >> 1, ra = (i & 1) * 2;
                float2 a = unpack_f16(Ah[m][kt][ra]);
                float2 b = unpack_f16(Ah[m][kt][ra + 1]);
                hf[i][0] = a.x; hf[i][1] = a.y; hf[i][2] = b.x; hf[i][3] = b.y;
            }
            const int row_g = rowbase + m * 16 + g;
#pragma unroll
            for (int o = 0; o < OUTD; o++) {
                float s0 = 0.0f, s1 = 0.0f;
#pragma unroll
                for (int i = 0; i < 8; i++) {
                    int j0 = i * 8 + 2 * q;
                    float2 w = *(const float2*)&sm->wout[o][j0];
                    s0 += hf[i][0] * w.x + hf[i][1] * w.y;
                    s1 += hf[i][2] * w.x + hf[i][3] * w.y;
                }
                s0 += __shfl_xor_sync(0xffffffffu, s0, 1);
                s0 += __shfl_xor_sync(0xffffffffu, s0, 2);
                s1 += __shfl_xor_sync(0xffffffffu, s1, 1);
                s1 += __shfl_xor_sync(0xffffffffu, s1, 2);
                if (q == 0) {
                    float bo = sm->bout[o];
                    out[(size_t)row_g * OUTD + o] = s0 + bo;
                    out[(size_t)(row_g + 8) * OUTD + o] = s1 + bo;
                }
            }
        }
    }
}

extern "C" void kernel_launch(void* const* d_in, const int* in_sizes, int n_in,
                              void* d_out, int out_size)
{
    const float* x    = (const float*)d_in[0];
    const float* Wih  = (const float*)d_in[1];
    const float* Whh  = (const float*)d_in[2];
    const float* bih  = (const float*)d_in[3];
    const float* bhh  = (const float*)d_in[4];
    const float* Wout = (const float*)d_in[5];
    const float* bout = (const float*)d_in[6];
    float* out = (float*)d_out;

    const int smem_bytes = (int)sizeof(SmemLayout);
    cudaFuncSetAttribute(gru_mma_kernel,
                         cudaFuncAttributeMaxDynamicSharedMemorySize, smem_bytes);

    gru_mma_kernel<<<NGRID, TPB, smem_bytes>>>(x, Wih, Whh, bih, bhh, Wout, bout, out);
}

// round 9
// speedup vs baseline: 1.1733x; 1.1733x over previous
#include <cuda_runtime.h>
#include <cuda_fp16.h>
#include <stdint.h>

#define BATCH 100000
#define SEQ   28
#define IND   28
#define HID   64
#define OUTD  10
#define TPB   128
#define WARPS (TPB/32)
#define MTILE (WARPS*16)                    // 64 batch rows per CTA
#define NGRID ((BATCH + MTILE - 1)/MTILE)   // 1563

// ---------------- shared memory ----------------
// B fragments as ldmatrix-ready 8x8 f16 matrices (layout identical to R5/R7).
struct SmemLayout {
    __half bxm[2 * 12 * 256];     // W_ih frags: 12288 B
    __half bhm[4 * 12 * 256];     // W_hh frags: 24576 B
    uint32_t bias_frag[32 * 4];   // f16x2 bias per (nt, q): cols (nt&7)*8+2q, +1
    float wout[OUTD][HID];
    float bout[OUTD];
};
#define OFF_BXM 0
#define OFF_BHM (2 * 12 * 512)
#define OFF_BF  (OFF_BHM + 4 * 12 * 512)

// ---------------- helpers ----------------
__device__ __forceinline__ uint32_t smem_u32(const void* p) {
    uint32_t a;
    asm("{ .reg .u64 t; cvta.to.shared.u64 t, %1; cvt.u32.u64 %0, t; }" : "=r"(a) : "l"(p));
    return a;
}
__device__ __forceinline__ uint32_t pack_f16(float e0, float e1) {
    uint32_t r;
    asm("cvt.rn.f16x2.f32 %0, %1, %2;" : "=r"(r) : "f"(e1), "f"(e0));
    return r;
}
__device__ __forceinline__ float2 unpack_f16(uint32_t p) {
    __half2 h = *reinterpret_cast<__half2*>(&p);
    return __half22float2(h);
}
__device__ __forceinline__ void ldsm_x4(uint32_t addr, uint32_t& r0, uint32_t& r1,
                                        uint32_t& r2, uint32_t& r3) {
    asm volatile("ldmatrix.sync.aligned.m8n8.x4.shared.b16 {%0,%1,%2,%3}, [%4];"
                 : "=r"(r0), "=r"(r1), "=r"(r2), "=r"(r3) : "r"(addr));
}
// f16-accumulator mma: C/D are 2x f16x2 regs
__device__ __forceinline__ void mma_h(uint32_t* c, const uint32_t* a, uint32_t b0, uint32_t b1) {
    asm volatile(
        "mma.sync.aligned.m16n8k16.row.col.f16.f16.f16.f16 "
        "{%0,%1}, {%2,%3,%4,%5}, {%6,%7}, {%0,%1};"
        : "+r"(c[0]), "+r"(c[1])
        : "r"(a[0]), "r"(a[1]), "r"(a[2]), "r"(a[3]), "r"(b0), "r"(b1));
}
__device__ __forceinline__ uint32_t tanh2u(uint32_t x) {
    uint32_t y;
    asm("tanh.approx.f16x2 %0, %1;" : "=r"(y) : "r"(x));
    return y;
}
__device__ __forceinline__ __half2 u2h(uint32_t u) { return *reinterpret_cast<__half2*>(&u); }
__device__ __forceinline__ uint32_t h2u(__half2 h) { return *reinterpret_cast<uint32_t*>(&h); }
__device__ __forceinline__ __half2 sig2(__half2 x) {
    const __half2 half_ = __float2half2_rn(0.5f);
    return __hfma2(half_, u2h(tanh2u(h2u(__hmul2(x, half_)))), half_);
}
// full GRU cell on a pair of hidden units (all f16x2, inputs are raw acc regs)
__device__ __forceinline__ uint32_t gru2(uint32_t rs, uint32_t zs, uint32_t is,
                                         uint32_t hs, uint32_t ho) {
    __half2 r = sig2(u2h(rs));
    __half2 z = sig2(u2h(zs));
    __half2 n = u2h(tanh2u(h2u(__hfma2(r, u2h(hs), u2h(is)))));
    return h2u(__hfma2(z, __hsub2(u2h(ho), n), n));   // (1-z)*n + z*h
}

__global__ void __launch_bounds__(TPB, 4)
gru_mma_kernel(const float* __restrict__ x,
               const float* __restrict__ Wih,
               const float* __restrict__ Whh,
               const float* __restrict__ bih,
               const float* __restrict__ bhh,
               const float* __restrict__ Wout,
               const float* __restrict__ bout,
               float* __restrict__ out)
{
    extern __shared__ char smraw[];
    SmemLayout* sm = (SmemLayout*)smraw;
    const int tid = threadIdx.x;

    // ---- stage W_ih fragments ----
    for (int s = tid; s < 2 * 12 * 256; s += TPB) {
        int kk = s & 7, g = (s >> 3) & 7, mat = (s >> 6) & 3;
        int blk = s >> 8;
        int pair = blk % 12, kt = blk / 12;
        int n = pair * 16 + (mat >> 1) * 8 + g;
        int k = kt * 16 + (mat & 1) * 8 + kk;
        float v = (k < IND) ? Wih[n * IND + k] : 0.0f;
        sm->bxm[s] = __float2half_rn(v);
    }
    // ---- stage W_hh fragments ----
    for (int s = tid; s < 4 * 12 * 256; s += TPB) {
        int kk = s & 7, g = (s >> 3) & 7, mat = (s >> 6) & 3;
        int blk = s >> 8;
        int pair = blk % 12, kt = blk / 12;
        int ntl = pair * 2 + (mat >> 1);
        int ngl = (ntl < 16 ? ntl : ntl + 8) * 8 + g;
        int row = (ngl < 128) ? ngl : ngl - 64;
        int k = kt * 16 + (mat & 1) * 8 + kk;
        sm->bhm[s] = __float2half_rn(Whh[row * HID + k]);
    }
    // ---- bias table (f16x2) in fragment order: nt 0-7 r, 8-15 z, 16-23 i_n, 24-31 h_n ----
    for (int s = tid; s < 32 * 4; s += TPB) {
        int nt = s >> 2, qq = s & 3;
        int j = (nt & 7) * 8 + 2 * qq;
        float b0, b1;
        if (nt < 8)       { b0 = bih[j] + bhh[j];         b1 = bih[j+1] + bhh[j+1]; }
        else if (nt < 16) { b0 = bih[64+j] + bhh[64+j];   b1 = bih[64+j+1] + bhh[64+j+1]; }
        else if (nt < 24) { b0 = bih[128+j];              b1 = bih[128+j+1]; }
        else              { b0 = bhh[128+j];              b1 = bhh[128+j+1]; }
        sm->bias_frag[s] = pack_f16(b0, b1);
    }
    for (int i = tid; i < OUTD * HID; i += TPB) ((float*)sm->wout)[i] = Wout[i];
    for (int i = tid; i < OUTD; i += TPB) sm->bout[i] = bout[i];
    __syncthreads();

    const int lane = tid & 31;
    const int wid = tid >> 5;
    const int q = lane & 3, g = lane >> 2;
    const int row0 = blockIdx.x * MTILE + wid * 16 + g;
    const int row1 = row0 + 8;
    const bool v0 = row0 < BATCH, v1 = row1 < BATCH;

    const uint32_t smb = smem_u32(smraw);
    const uint32_t bx_base = smb + OFF_BXM + (uint32_t)lane * 16u;
    const uint32_t bh_base = smb + OFF_BHM + (uint32_t)lane * 16u;
    const uint32_t bf_base = smb + OFF_BF + (uint32_t)q * 4u;

    uint32_t acc[32][2];        // f16x2 accumulators (raw regs)
    uint32_t Ax[2][4], Ah[4][4];
#pragma unroll
    for (int kt = 0; kt < 4; kt++)
#pragma unroll
        for (int r = 0; r < 4; r++) Ah[kt][r] = 0u;

    const float* xr0 = x + (size_t)(v0 ? row0 : 0) * (SEQ * IND);
    const float* xr1 = x + (size_t)(v1 ? row1 : 0) * (SEQ * IND);

#pragma unroll 1
    for (int t = 0; t < SEQ; t++) {
        // ---- load x_t and convert immediately to f16 A-fragments ----
#pragma unroll
        for (int kt = 0; kt < 2; kt++)
#pragma unroll
            for (int half = 0; half < 2; half++) {
                const int kb = kt * 16 + 2 * q + half * 8;
                float2 p0 = make_float2(0.0f, 0.0f), p1 = p0;
                const bool kv = kb < IND;
                if (v0 && kv) p0 = *(const float2*)(xr0 + t * IND + kb);
                if (v1 && kv) p1 = *(const float2*)(xr1 + t * IND + kb);
                Ax[kt][half * 2 + 0] = pack_f16(p0.x, p0.y);
                Ax[kt][half * 2 + 1] = pack_f16(p1.x, p1.y);
            }

        // ---- init accumulators from f16x2 bias table ----
#pragma unroll
        for (int nt = 0; nt < 32; nt++) {
            uint32_t bf;
            asm volatile("ld.shared.b32 %0, [%1];" : "=r"(bf)
                         : "r"(bf_base + (uint32_t)nt * 16u));
            acc[nt][0] = bf; acc[nt][1] = bf;
        }

        // ---- h GEMM: D[:,{0:128,192:256}] += h @ W_hh^T ----
#pragma unroll
        for (int kt = 0; kt < 4; kt++) {
#pragma unroll
            for (int p = 0; p < 12; p++) {
                uint32_t b0, b1, b2, b3;
                ldsm_x4(bh_base + (uint32_t)(kt * 12 + p) * 512u, b0, b1, b2, b3);
                const int ntl_e = 2 * p, ntl_o = 2 * p + 1;
                const int nt_e = (ntl_e < 16) ? ntl_e : ntl_e + 8;
                const int nt_o = (ntl_o < 16) ? ntl_o : ntl_o + 8;
                mma_h(acc[nt_e], Ah[kt], b0, b1);
                mma_h(acc[nt_o], Ah[kt], b2, b3);
            }
        }

        // ---- x GEMM: D[:,0:192] += x @ W_ih^T ----
#pragma unroll
        for (int kt = 0; kt < 2; kt++) {
#pragma unroll
            for (int p = 0; p < 12; p++) {
                uint32_t b0, b1, b2, b3;
                ldsm_x4(bx_base + (uint32_t)(kt * 12 + p) * 512u, b0, b1, b2, b3);
                mma_h(acc[2 * p],     Ax[kt], b0, b1);
                mma_h(acc[2 * p + 1], Ax[kt], b2, b3);
            }
        }

        // ---- epilogue: all-f16x2 gates directly on acc regs; h_new -> Ah ----
#pragma unroll
        for (int i = 0; i < 8; i++) {
            const int kt = i >> 1;
            const int ra = (i & 1) * 2;
            Ah[kt][ra]     = gru2(acc[i][0], acc[8 + i][0], acc[16 + i][0],
                                  acc[24 + i][0], Ah[kt][ra]);
            Ah[kt][ra + 1] = gru2(acc[i][1], acc[8 + i][1], acc[16 + i][1],
                                  acc[24 + i][1], Ah[kt][ra + 1]);
        }
    }

    // ---- output projection: out = hT @ W_out^T + b_out ----
    float hf[8][4];
#pragma unroll
    for (int i = 0; i < 8; i++) {
        const int kt = i >> 1, ra = (i & 1) * 2;
        float2 a = unpack_f16(Ah[kt][ra]);
        float2 b = unpack_f16(Ah[kt][ra + 1]);
        hf[i][0] = a.x; hf[i][1] = a.y; hf[i][2] = b.x; hf[i][3] = b.y;
    }
#pragma unroll
    for (int o = 0; o < OUTD; o++) {
        float s0 = 0.0f, s1 = 0.0f;
#pragma unroll
        for (int i = 0; i < 8; i++) {
            int j0 = i * 8 + 2 * q;
            float2 w = *(const float2*)&sm->wout[o][j0];
            s0 += hf[i][0] * w.x + hf[i][1] * w.y;
            s1 += hf[i][2] * w.x + hf[i][3] * w.y;
        }
        s0 += __shfl_xor_sync(0xffffffffu, s0, 1);
        s0 += __shfl_xor_sync(0xffffffffu, s0, 2);
        s1 += __shfl_xor_sync(0xffffffffu, s1, 1);
        s1 += __shfl_xor_sync(0xffffffffu, s1, 2);
        if (q == 0) {
            float bo = sm->bout[o];
            if (v0) out[(size_t)row0 * OUTD + o] = s0 + bo;
            if (v1) out[(size_t)row1 * OUTD + o] = s1 + bo;
        }
    }
}

extern "C" void kernel_launch(void* const* d_in, const int* in_sizes, int n_in,
                              void* d_out, int out_size)
{
    const float* x    = (const float*)d_in[0];
    const float* Wih  = (const float*)d_in[1];
    const float* Whh  = (const float*)d_in[2];
    const float* bih  = (const float*)d_in[3];
    const float* bhh  = (const float*)d_in[4];
    const float* Wout = (const float*)d_in[5];
    const float* bout = (const float*)d_in[6];
    float* out = (float*)d_out;

    const int smem_bytes = (int)sizeof(SmemLayout);
    cudaFuncSetAttribute(gru_mma_kernel,
                         cudaFuncAttributeMaxDynamicSharedMemorySize, smem_bytes);

    gru_mma_kernel<<<NGRID, TPB, smem_bytes>>>(x, Wih, Whh, bih, bhh, Wout, bout, out);
}